// round 3
// baseline (speedup 1.0000x reference)
#include <cuda_runtime.h>
#include <math.h>

// Problem constants (fixed by the dataset shapes)
#define Bq    8
#define Aq    64
#define DE    128
#define DH    64
#define Mq    512            // N*L = 8*64
#define ZDIM  128
#define ZE    64
#define ZH    64
#define MAXN  0.99999f       // (1 - 1e-5)/sqrt(c), c = 1
#define ARGC  0.9999999f     // 1 - 1e-7

// Scratch (device globals: no allocation in kernel_launch)
__device__ float g_dH2[Bq * Mq];              // 16 KB
__device__ float g_logv[Bq * Mq * DH];        // 1 MB

__device__ __forceinline__ float wredsum(float v) {
#pragma unroll
    for (int o = 16; o; o >>= 1) v += __shfl_xor_sync(0xffffffffu, v, o);
    return v;
}

// ---------------------------------------------------------------------------
// Kernel 1: per (b, m) hyperbolic precompute.
// One warp per (b,m); lane owns dims (2*lane, 2*lane+1) of dh=64.
// u = mobius_add(-x, y) is shared between dH^2 and log-map.
// ---------------------------------------------------------------------------
__global__ __launch_bounds__(128) void k_hyp(
    const float* __restrict__ curr_hyp,   // [B, DH]
    const float* __restrict__ demo_hyp)   // [B, M, DH]
{
    int warp = threadIdx.x >> 5, lane = threadIdx.x & 31;
    int idx  = blockIdx.x * 4 + warp;     // [0, B*M)
    int b    = idx / Mq;

    const float2 xv = ((const float2*)(curr_hyp + (size_t)b * DH))[lane];
    const float2 yv = ((const float2*)(demo_hyp + (size_t)idx * DH))[lane];
    float x0 = xv.x, x1 = xv.y, y0 = yv.x, y1 = yv.y;

    // project x to ball
    float xn2   = wredsum(x0 * x0 + x1 * x1);
    float xnorm = fmaxf(sqrtf(xn2), 1e-15f);
    float sx    = xnorm > MAXN ? MAXN / xnorm : 1.0f;
    x0 *= sx; x1 *= sx;
    float x2 = xn2 * sx * sx;
    // project y to ball
    float yn2   = wredsum(y0 * y0 + y1 * y1);
    float ynorm = fmaxf(sqrtf(yn2), 1e-15f);
    float sy    = ynorm > MAXN ? MAXN / ynorm : 1.0f;
    y0 *= sy; y1 *= sy;
    float y2 = yn2 * sy * sy;

    float xy = wredsum(x0 * y0 + x1 * y1);

    // u = mobius_add(a=-x, y):
    //   num = (1 + 2*a.y + |y|^2)*a + (1 - |a|^2)*y ; den = 1 + 2*a.y + |a|^2|y|^2
    float cA  = 1.0f - 2.0f * xy + y2;
    float cY  = 1.0f - x2;
    float den = 1.0f - 2.0f * xy + x2 * y2;
    float id  = 1.0f / fmaxf(den, 1e-15f);
    float u0  = (cA * (-x0) + cY * y0) * id;
    float u1  = (cA * (-x1) + cY * y1) * id;

    float un2   = wredsum(u0 * u0 + u1 * u1);
    float unorm = fmaxf(sqrtf(un2), 1e-15f);
    float arg   = fminf(unorm, ARGC);
    float at    = atanhf(arg);

    float lam   = 2.0f / fmaxf(1.0f - x2, 1e-15f);
    float scale = (2.0f / lam) * at / unorm;   // includes /unorm (u_dir)

    ((float2*)(g_logv + (size_t)idx * DH))[lane] = make_float2(scale * u0, scale * u1);
    if (lane == 0) { float d = 2.0f * at; g_dH2[idx] = d * d; }
}

// ---------------------------------------------------------------------------
// Kernel 2: one block per (b, a). Fused online-softmax attention over m,
// Euclidean + log-vec aggregation, exp-map, projections, LayerNorm.
// ---------------------------------------------------------------------------
__global__ __launch_bounds__(128) void k_attn(
    const float* __restrict__ curr_rho,   // [B, A, DE]
    const float* __restrict__ curr_hyp,   // [B, DH]
    const float* __restrict__ demo_rho,   // [B, M, A, DE]
    const float* __restrict__ We,         // [ZE, DE]
    const float* __restrict__ Wh,         // [ZH, DH]
    const float* __restrict__ gamma,      // [ZDIM]
    const float* __restrict__ beta,       // [ZDIM]
    float* __restrict__ out)              // [B, A, ZDIM]
{
    int b = blockIdx.x >> 6, a = blockIdx.x & 63;
    int tid = threadIdx.x, warp = tid >> 5, lane = tid & 31;

    // query rho slice (d = 4*lane .. 4*lane+3)
    const float4 cr = ((const float4*)(curr_rho + ((size_t)b * Aq + a) * DE))[lane];

    float  mx = -INFINITY, sm = 0.0f;
    float4 ea = make_float4(0.f, 0.f, 0.f, 0.f);
    float2 va = make_float2(0.f, 0.f);

    const float* dH2b = g_dH2 + (size_t)b * Mq;

    // Software-pipelined (depth 2) online-softmax mainloop; warp w owns m = w, w+4, ...
    int m = warp;
    float4 dm = ((const float4*)(demo_rho + (((size_t)b * Mq + m) * Aq + a) * DE))[lane];
    float2 lv = ((const float2*)(g_logv + ((size_t)b * Mq + m) * DH))[lane];
    while (m < Mq) {
        int mn = m + 4;
        float4 dmn; float2 lvn;
        if (mn < Mq) {
            dmn = ((const float4*)(demo_rho + (((size_t)b * Mq + mn) * Aq + a) * DE))[lane];
            lvn = ((const float2*)(g_logv + ((size_t)b * Mq + mn) * DH))[lane];
        } else {
            dmn = make_float4(0.f, 0.f, 0.f, 0.f);
            lvn = make_float2(0.f, 0.f);
        }
        float dx = cr.x - dm.x, dy = cr.y - dm.y, dz = cr.z - dm.z, dw = cr.w - dm.w;
        float esq = wredsum(dx * dx + dy * dy + dz * dz + dw * dw);
        float score = -(dH2b[m] + esq);                 // LH = LE = TAU = 1
        float nm   = fmaxf(mx, score);
        float corr = __expf(mx - nm);                   // exp(-inf)=0 on first iter
        float w    = __expf(score - nm);
        sm   = sm   * corr + w;
        ea.x = ea.x * corr + w * dm.x;
        ea.y = ea.y * corr + w * dm.y;
        ea.z = ea.z * corr + w * dm.z;
        ea.w = ea.w * corr + w * dm.w;
        va.x = va.x * corr + w * lv.x;
        va.y = va.y * corr + w * lv.y;
        mx = nm;
        dm = dmn; lv = lvn; m = mn;
    }

    // ---- merge 4 warps ----
    __shared__ float s_mx[4], s_sm[4], s_e[4][DE], s_v[4][DH];
    __shared__ float s_eout[DE], s_vv[DH], s_h[DH], s_wred[4];

    s_e[warp][4 * lane + 0] = ea.x;  s_e[warp][4 * lane + 1] = ea.y;
    s_e[warp][4 * lane + 2] = ea.z;  s_e[warp][4 * lane + 3] = ea.w;
    s_v[warp][2 * lane + 0] = va.x;  s_v[warp][2 * lane + 1] = va.y;
    if (lane == 0) { s_mx[warp] = mx; s_sm[warp] = sm; }
    __syncthreads();

    float gmax = fmaxf(fmaxf(s_mx[0], s_mx[1]), fmaxf(s_mx[2], s_mx[3]));
    float c0 = __expf(s_mx[0] - gmax), c1 = __expf(s_mx[1] - gmax);
    float c2 = __expf(s_mx[2] - gmax), c3 = __expf(s_mx[3] - gmax);
    float inv = 1.0f / (s_sm[0] * c0 + s_sm[1] * c1 + s_sm[2] * c2 + s_sm[3] * c3);

    s_eout[tid] = (s_e[0][tid] * c0 + s_e[1][tid] * c1 +
                   s_e[2][tid] * c2 + s_e[3][tid] * c3) * inv;
    if (tid < DH)
        s_vv[tid] = (s_v[0][tid] * c0 + s_v[1][tid] * c1 +
                     s_v[2][tid] * c2 + s_v[3][tid] * c3) * inv;
    __syncthreads();

    // ---- exp-map (warp 0; lane owns dims lane and lane+32) ----
    if (warp == 0) {
        float x0 = curr_hyp[b * DH + lane], x1 = curr_hyp[b * DH + lane + 32];
        float xn2   = wredsum(x0 * x0 + x1 * x1);
        float xnorm = fmaxf(sqrtf(xn2), 1e-15f);
        float sx    = xnorm > MAXN ? MAXN / xnorm : 1.0f;
        x0 *= sx; x1 *= sx;
        float x2  = xn2 * sx * sx;
        float lam = 2.0f / fmaxf(1.0f - x2, 1e-15f);

        float v0 = s_vv[lane], v1 = s_vv[lane + 32];
        float vn2    = wredsum(v0 * v0 + v1 * v1);
        float vnorm  = fmaxf(sqrtf(vn2), 1e-15f);
        float factor = tanhf(lam * vnorm * 0.5f);
        float f      = factor / vnorm;
        float y0 = v0 * f, y1 = v1 * f;

        // project y
        float yn2   = wredsum(y0 * y0 + y1 * y1);
        float ynorm = fmaxf(sqrtf(yn2), 1e-15f);
        float sy    = ynorm > MAXN ? MAXN / ynorm : 1.0f;
        y0 *= sy; y1 *= sy;
        float y2s = yn2 * sy * sy;

        float xy  = wredsum(x0 * y0 + x1 * y1);
        float cA  = 1.0f + 2.0f * xy + y2s;
        float cY  = 1.0f - x2;
        float den = 1.0f + 2.0f * xy + x2 * y2s;
        float id  = 1.0f / fmaxf(den, 1e-15f);
        float o0  = (cA * x0 + cY * y0) * id;
        float o1  = (cA * x1 + cY * y1) * id;

        // project output
        float on2   = wredsum(o0 * o0 + o1 * o1);
        float onorm = fmaxf(sqrtf(on2), 1e-15f);
        float so    = onorm > MAXN ? MAXN / onorm : 1.0f;
        s_h[lane] = o0 * so; s_h[lane + 32] = o1 * so;
    }
    __syncthreads();

    // ---- projections z = [e_out @ We^T, h_out @ Wh^T] ----
    float z;
    if (tid < ZE) {
        const float4* wr = (const float4*)(We + (size_t)tid * DE);
        float acc = 0.f;
#pragma unroll
        for (int k = 0; k < DE / 4; k++) {
            float4 wv = wr[k];
            acc += wv.x * s_eout[4 * k]     + wv.y * s_eout[4 * k + 1]
                 + wv.z * s_eout[4 * k + 2] + wv.w * s_eout[4 * k + 3];
        }
        z = acc;
    } else {
        const float4* wr = (const float4*)(Wh + (size_t)(tid - ZE) * DH);
        float acc = 0.f;
#pragma unroll
        for (int k = 0; k < DH / 4; k++) {
            float4 wv = wr[k];
            acc += wv.x * s_h[4 * k]     + wv.y * s_h[4 * k + 1]
                 + wv.z * s_h[4 * k + 2] + wv.w * s_h[4 * k + 3];
        }
        z = acc;
    }

    // ---- LayerNorm over ZDIM = 128 threads ----
    float p = wredsum(z);
    if (lane == 0) s_wred[warp] = p;
    __syncthreads();
    float mean = (s_wred[0] + s_wred[1] + s_wred[2] + s_wred[3]) * (1.0f / ZDIM);
    float dz = z - mean;
    float q = wredsum(dz * dz);
    __syncthreads();
    if (lane == 0) s_wred[warp] = q;
    __syncthreads();
    float var = (s_wred[0] + s_wred[1] + s_wred[2] + s_wred[3]) * (1.0f / ZDIM);

    out[(size_t)blockIdx.x * ZDIM + tid] = dz / sqrtf(var + 1e-5f) * gamma[tid] + beta[tid];
}

// ---------------------------------------------------------------------------
extern "C" void kernel_launch(void* const* d_in, const int* in_sizes, int n_in,
                              void* d_out, int out_size)
{
    const float* curr_rho = (const float*)d_in[0];   // [B,A,de]
    const float* curr_hyp = (const float*)d_in[1];   // [B,dh]
    const float* demo_rho = (const float*)d_in[2];   // [B,N,L,A,de]
    const float* demo_hyp = (const float*)d_in[3];   // [B,N,L,dh]
    const float* We       = (const float*)d_in[4];   // [z_e,de]
    const float* Wh       = (const float*)d_in[5];   // [z_h,dh]
    const float* gamma    = (const float*)d_in[6];   // [z]
    const float* beta     = (const float*)d_in[7];   // [z]
    float* out = (float*)d_out;

    k_hyp<<<(Bq * Mq) / 4, 128>>>(curr_hyp, demo_hyp);
    k_attn<<<Bq * Aq, 128>>>(curr_rho, curr_hyp, demo_rho, We, Wh, gamma, beta, out);
}

// round 4
// speedup vs baseline: 1.4594x; 1.4594x over previous
#include <cuda_runtime.h>
#include <math.h>

// Problem constants (fixed by the dataset shapes)
#define Bq    8
#define Aq    64
#define DE    128
#define DH    64
#define Mq    512            // N*L = 8*64
#define ZDIM  128
#define ZE    64
#define ZH    64
#define SPLIT 4              // m-splits per (b,a)
#define MPW   32             // m-iterations per warp = (Mq/SPLIT)/4
#define MAXN  0.99999f       // (1 - 1e-5)/sqrt(c), c = 1
#define ARGC  0.9999999f     // 1 - 1e-7

// Scratch (device globals: no allocation in kernel_launch)
__device__ float g_dH2[Bq * Mq];                       // 16 KB
__device__ float g_logv[Bq * Mq * DH];                 // 1 MB
__device__ float g_pmx[Bq * Aq * SPLIT];               // partial max
__device__ float g_psm[Bq * Aq * SPLIT];               // partial sum-exp
__device__ float g_pe [Bq * Aq * SPLIT * DE];          // 1 MB partial e-acc
__device__ float g_pv [Bq * Aq * SPLIT * DH];          // 0.5 MB partial v-acc

__device__ __forceinline__ float wredsum(float v) {
#pragma unroll
    for (int o = 16; o; o >>= 1) v += __shfl_xor_sync(0xffffffffu, v, o);
    return v;
}

// ---------------------------------------------------------------------------
// Kernel 1: per (b, m) hyperbolic precompute (unchanged from R3 — ~2 µs).
// ---------------------------------------------------------------------------
__global__ __launch_bounds__(128) void k_hyp(
    const float* __restrict__ curr_hyp,   // [B, DH]
    const float* __restrict__ demo_hyp)   // [B, M, DH]
{
    int warp = threadIdx.x >> 5, lane = threadIdx.x & 31;
    int idx  = blockIdx.x * 4 + warp;     // [0, B*M)
    int b    = idx / Mq;

    const float2 xv = ((const float2*)(curr_hyp + (size_t)b * DH))[lane];
    const float2 yv = ((const float2*)(demo_hyp + (size_t)idx * DH))[lane];
    float x0 = xv.x, x1 = xv.y, y0 = yv.x, y1 = yv.y;

    float xn2   = wredsum(x0 * x0 + x1 * x1);
    float xnorm = fmaxf(sqrtf(xn2), 1e-15f);
    float sx    = xnorm > MAXN ? MAXN / xnorm : 1.0f;
    x0 *= sx; x1 *= sx;
    float x2 = xn2 * sx * sx;

    float yn2   = wredsum(y0 * y0 + y1 * y1);
    float ynorm = fmaxf(sqrtf(yn2), 1e-15f);
    float sy    = ynorm > MAXN ? MAXN / ynorm : 1.0f;
    y0 *= sy; y1 *= sy;
    float y2 = yn2 * sy * sy;

    float xy = wredsum(x0 * y0 + x1 * y1);

    float cA  = 1.0f - 2.0f * xy + y2;
    float cY  = 1.0f - x2;
    float den = 1.0f - 2.0f * xy + x2 * y2;
    float id  = 1.0f / fmaxf(den, 1e-15f);
    float u0  = (cA * (-x0) + cY * y0) * id;
    float u1  = (cA * (-x1) + cY * y1) * id;

    float un2   = wredsum(u0 * u0 + u1 * u1);
    float unorm = fmaxf(sqrtf(un2), 1e-15f);
    float arg   = fminf(unorm, ARGC);
    float at    = atanhf(arg);

    float lam   = 2.0f / fmaxf(1.0f - x2, 1e-15f);
    float scale = (2.0f / lam) * at / unorm;

    ((float2*)(g_logv + (size_t)idx * DH))[lane] = make_float2(scale * u0, scale * u1);
    if (lane == 0) { float d = 2.0f * at; g_dH2[idx] = d * d; }
}

// ---------------------------------------------------------------------------
// Kernel 2: partial online-softmax attention. One block per (b, a, s);
// block covers m in [s*128, (s+1)*128), warp w handles m = s*128 + w + 4*i.
// Writes block-level partial (max, sum, e[128], v[64]) to scratch.
// ---------------------------------------------------------------------------
__global__ __launch_bounds__(128) void k_attn_part(
    const float* __restrict__ curr_rho,   // [B, A, DE]
    const float* __restrict__ demo_rho)   // [B, M, A, DE]
{
    int bas = blockIdx.x;                 // ((b*64 + a)*SPLIT + s)
    int s   = bas & (SPLIT - 1);
    int ba  = bas >> 2;
    int b   = ba >> 6, a = ba & 63;
    int tid = threadIdx.x, warp = tid >> 5, lane = tid & 31;

    const float4 cr = ((const float4*)(curr_rho + ((size_t)b * Aq + a) * DE))[lane];

    const float* dH2b  = g_dH2  + (size_t)b * Mq;
    const float* rho_b = demo_rho + ((size_t)b * Mq * Aq + a) * DE;
    const float* lv_b  = g_logv + (size_t)b * Mq * DH;

    int m0 = s * (Mq / SPLIT) + warp;     // this warp's first m; stride 4

    float  mx = -INFINITY, sm = 0.0f;
    float4 ea = make_float4(0.f, 0.f, 0.f, 0.f);
    float2 va = make_float2(0.f, 0.f);

    // double-buffered mainloop, MPW = 32 iterations
    float4 dmb[2]; float2 lvb[2];
    dmb[0] = ((const float4*)(rho_b + (size_t)m0 * Aq * DE))[lane];
    lvb[0] = ((const float2*)(lv_b + (size_t)m0 * DH))[lane];
    dmb[1] = ((const float4*)(rho_b + (size_t)(m0 + 4) * Aq * DE))[lane];
    lvb[1] = ((const float2*)(lv_b + (size_t)(m0 + 4) * DH))[lane];

#pragma unroll 4
    for (int i = 0; i < MPW; ++i) {
        float4 dm = dmb[i & 1]; float2 lv = lvb[i & 1];
        int mn = m0 + 4 * (i + 2);
        if (i + 2 < MPW) {
            dmb[i & 1] = ((const float4*)(rho_b + (size_t)mn * Aq * DE))[lane];
            lvb[i & 1] = ((const float2*)(lv_b + (size_t)mn * DH))[lane];
        }
        float dx = cr.x - dm.x, dy = cr.y - dm.y, dz = cr.z - dm.z, dw = cr.w - dm.w;
        float esq = wredsum(fmaf(dx, dx, fmaf(dy, dy, fmaf(dz, dz, dw * dw))));
        float score = -(dH2b[m0 + 4 * i] + esq);        // LH = LE = TAU = 1
        float nm   = fmaxf(mx, score);
        float corr = __expf(mx - nm);                   // exp(-inf)=0 first iter
        float w    = __expf(score - nm);
        sm   = sm   * corr + w;
        ea.x = ea.x * corr + w * dm.x;
        ea.y = ea.y * corr + w * dm.y;
        ea.z = ea.z * corr + w * dm.z;
        ea.w = ea.w * corr + w * dm.w;
        va.x = va.x * corr + w * lv.x;
        va.y = va.y * corr + w * lv.y;
        mx = nm;
    }

    // ---- merge 4 warps, write block partial (unnormalized, at block max) ----
    __shared__ float s_mx[4], s_sm[4], s_e[4][DE], s_v[4][DH];
    s_e[warp][4 * lane + 0] = ea.x;  s_e[warp][4 * lane + 1] = ea.y;
    s_e[warp][4 * lane + 2] = ea.z;  s_e[warp][4 * lane + 3] = ea.w;
    s_v[warp][2 * lane + 0] = va.x;  s_v[warp][2 * lane + 1] = va.y;
    if (lane == 0) { s_mx[warp] = mx; s_sm[warp] = sm; }
    __syncthreads();

    float gmax = fmaxf(fmaxf(s_mx[0], s_mx[1]), fmaxf(s_mx[2], s_mx[3]));
    float c0 = __expf(s_mx[0] - gmax), c1 = __expf(s_mx[1] - gmax);
    float c2 = __expf(s_mx[2] - gmax), c3 = __expf(s_mx[3] - gmax);

    g_pe[(size_t)bas * DE + tid] = s_e[0][tid] * c0 + s_e[1][tid] * c1 +
                                   s_e[2][tid] * c2 + s_e[3][tid] * c3;
    if (tid < DH)
        g_pv[(size_t)bas * DH + tid] = s_v[0][tid] * c0 + s_v[1][tid] * c1 +
                                       s_v[2][tid] * c2 + s_v[3][tid] * c3;
    if (tid == 0) {
        g_pmx[bas] = gmax;
        g_psm[bas] = s_sm[0] * c0 + s_sm[1] * c1 + s_sm[2] * c2 + s_sm[3] * c3;
    }
}

// ---------------------------------------------------------------------------
// Kernel 3: merge SPLIT partials per (b,a); exp-map, projections, LayerNorm.
// ---------------------------------------------------------------------------
__global__ __launch_bounds__(128) void k_final(
    const float* __restrict__ curr_hyp,   // [B, DH]
    const float* __restrict__ We,         // [ZE, DE]
    const float* __restrict__ Wh,         // [ZH, DH]
    const float* __restrict__ gamma,      // [ZDIM]
    const float* __restrict__ beta,       // [ZDIM]
    float* __restrict__ out)              // [B, A, ZDIM]
{
    int ba = blockIdx.x;                  // b*64 + a
    int b  = ba >> 6;
    int tid = threadIdx.x, warp = tid >> 5, lane = tid & 31;

    __shared__ float s_eout[DE], s_vv[DH], s_h[DH], s_wred[4];

    // combine SPLIT partials with global-max rescale
    float mx0 = g_pmx[ba * SPLIT + 0], mx1 = g_pmx[ba * SPLIT + 1];
    float mx2 = g_pmx[ba * SPLIT + 2], mx3 = g_pmx[ba * SPLIT + 3];
    float G = fmaxf(fmaxf(mx0, mx1), fmaxf(mx2, mx3));
    float c0 = __expf(mx0 - G), c1 = __expf(mx1 - G);
    float c2 = __expf(mx2 - G), c3 = __expf(mx3 - G);
    float inv = 1.0f / (g_psm[ba * SPLIT + 0] * c0 + g_psm[ba * SPLIT + 1] * c1 +
                        g_psm[ba * SPLIT + 2] * c2 + g_psm[ba * SPLIT + 3] * c3);

    s_eout[tid] = (g_pe[((size_t)ba * SPLIT + 0) * DE + tid] * c0 +
                   g_pe[((size_t)ba * SPLIT + 1) * DE + tid] * c1 +
                   g_pe[((size_t)ba * SPLIT + 2) * DE + tid] * c2 +
                   g_pe[((size_t)ba * SPLIT + 3) * DE + tid] * c3) * inv;
    if (tid < DH)
        s_vv[tid] = (g_pv[((size_t)ba * SPLIT + 0) * DH + tid] * c0 +
                     g_pv[((size_t)ba * SPLIT + 1) * DH + tid] * c1 +
                     g_pv[((size_t)ba * SPLIT + 2) * DH + tid] * c2 +
                     g_pv[((size_t)ba * SPLIT + 3) * DH + tid] * c3) * inv;
    __syncthreads();

    // ---- exp-map (warp 0; lane owns dims lane and lane+32) ----
    if (warp == 0) {
        float x0 = curr_hyp[b * DH + lane], x1 = curr_hyp[b * DH + lane + 32];
        float xn2   = wredsum(x0 * x0 + x1 * x1);
        float xnorm = fmaxf(sqrtf(xn2), 1e-15f);
        float sx    = xnorm > MAXN ? MAXN / xnorm : 1.0f;
        x0 *= sx; x1 *= sx;
        float x2  = xn2 * sx * sx;
        float lam = 2.0f / fmaxf(1.0f - x2, 1e-15f);

        float v0 = s_vv[lane], v1 = s_vv[lane + 32];
        float vn2    = wredsum(v0 * v0 + v1 * v1);
        float vnorm  = fmaxf(sqrtf(vn2), 1e-15f);
        float factor = tanhf(lam * vnorm * 0.5f);
        float f      = factor / vnorm;
        float y0 = v0 * f, y1 = v1 * f;

        float yn2   = wredsum(y0 * y0 + y1 * y1);
        float ynorm = fmaxf(sqrtf(yn2), 1e-15f);
        float sy    = ynorm > MAXN ? MAXN / ynorm : 1.0f;
        y0 *= sy; y1 *= sy;
        float y2s = yn2 * sy * sy;

        float xy  = wredsum(x0 * y0 + x1 * y1);
        float cA  = 1.0f + 2.0f * xy + y2s;
        float cY  = 1.0f - x2;
        float den = 1.0f + 2.0f * xy + x2 * y2s;
        float id  = 1.0f / fmaxf(den, 1e-15f);
        float o0  = (cA * x0 + cY * y0) * id;
        float o1  = (cA * x1 + cY * y1) * id;

        float on2   = wredsum(o0 * o0 + o1 * o1);
        float onorm = fmaxf(sqrtf(on2), 1e-15f);
        float so    = onorm > MAXN ? MAXN / onorm : 1.0f;
        s_h[lane] = o0 * so; s_h[lane + 32] = o1 * so;
    }
    __syncthreads();

    // ---- projections z = [e_out @ We^T, h_out @ Wh^T] ----
    float z;
    if (tid < ZE) {
        const float4* wr = (const float4*)(We + (size_t)tid * DE);
        float acc = 0.f;
#pragma unroll
        for (int k = 0; k < DE / 4; k++) {
            float4 wv = wr[k];
            acc += wv.x * s_eout[4 * k]     + wv.y * s_eout[4 * k + 1]
                 + wv.z * s_eout[4 * k + 2] + wv.w * s_eout[4 * k + 3];
        }
        z = acc;
    } else {
        const float4* wr = (const float4*)(Wh + (size_t)(tid - ZE) * DH);
        float acc = 0.f;
#pragma unroll
        for (int k = 0; k < DH / 4; k++) {
            float4 wv = wr[k];
            acc += wv.x * s_h[4 * k]     + wv.y * s_h[4 * k + 1]
                 + wv.z * s_h[4 * k + 2] + wv.w * s_h[4 * k + 3];
        }
        z = acc;
    }

    // ---- LayerNorm over ZDIM = 128 threads ----
    float p = wredsum(z);
    if (lane == 0) s_wred[warp] = p;
    __syncthreads();
    float mean = (s_wred[0] + s_wred[1] + s_wred[2] + s_wred[3]) * (1.0f / ZDIM);
    float dz = z - mean;
    float q = wredsum(dz * dz);
    __syncthreads();
    if (lane == 0) s_wred[warp] = q;
    __syncthreads();
    float var = (s_wred[0] + s_wred[1] + s_wred[2] + s_wred[3]) * (1.0f / ZDIM);

    out[(size_t)ba * ZDIM + tid] = dz / sqrtf(var + 1e-5f) * gamma[tid] + beta[tid];
}

// ---------------------------------------------------------------------------
extern "C" void kernel_launch(void* const* d_in, const int* in_sizes, int n_in,
                              void* d_out, int out_size)
{
    const float* curr_rho = (const float*)d_in[0];   // [B,A,de]
    const float* curr_hyp = (const float*)d_in[1];   // [B,dh]
    const float* demo_rho = (const float*)d_in[2];   // [B,N,L,A,de]
    const float* demo_hyp = (const float*)d_in[3];   // [B,N,L,dh]
    const float* We       = (const float*)d_in[4];   // [z_e,de]
    const float* Wh       = (const float*)d_in[5];   // [z_h,dh]
    const float* gamma    = (const float*)d_in[6];   // [z]
    const float* beta     = (const float*)d_in[7];   // [z]
    float* out = (float*)d_out;

    k_hyp<<<(Bq * Mq) / 4, 128>>>(curr_hyp, demo_hyp);
    k_attn_part<<<Bq * Aq * SPLIT, 128>>>(curr_rho, demo_rho);
    k_final<<<Bq * Aq, 128>>>(curr_hyp, We, Wh, gamma, beta, out);
}

// round 5
// speedup vs baseline: 1.7477x; 1.1975x over previous
#include <cuda_runtime.h>
#include <math.h>
#include <stdint.h>

// Problem constants (fixed by the dataset shapes)
#define Bq    8
#define Aq    64
#define DE    128
#define DH    64
#define Mq    512            // N*L = 8*64
#define ZDIM  128
#define ZE    64
#define ZH    64
#define SPLIT 2              // m-splits per (b,a)
#define MBLK  (Mq / SPLIT)   // 256 m per block
#define MPW   (MBLK / 4)     // 64 m per warp
#define DEPTH 8              // cp.async pipeline stages
#define MAXN  0.99999f       // (1 - 1e-5)/sqrt(c), c = 1
#define ARGC  0.9999999f     // 1 - 1e-7

// Scratch (device globals: no allocation in kernel_launch)
__device__ float g_dH2[Bq * Mq];                       // 16 KB
__device__ float g_logv[Bq * Mq * DH];                 // 1 MB
__device__ float g_pmx[Bq * Aq * SPLIT];               // partial max
__device__ float g_psm[Bq * Aq * SPLIT];               // partial sum-exp
__device__ float g_pe [Bq * Aq * SPLIT * DE];          // partial e-acc
__device__ float g_pv [Bq * Aq * SPLIT * DH];          // partial v-acc

__device__ __forceinline__ float wredsum(float v) {
#pragma unroll
    for (int o = 16; o; o >>= 1) v += __shfl_xor_sync(0xffffffffu, v, o);
    return v;
}

__device__ __forceinline__ uint32_t smem_u32(const void* p) {
    return (uint32_t)__cvta_generic_to_shared(p);
}
__device__ __forceinline__ void cp_async16(uint32_t dst, const void* src) {
    asm volatile("cp.async.cg.shared.global [%0], [%1], 16;\n" :: "r"(dst), "l"(src));
}
__device__ __forceinline__ void cp_async8(uint32_t dst, const void* src) {
    asm volatile("cp.async.ca.shared.global [%0], [%1], 8;\n" :: "r"(dst), "l"(src));
}
__device__ __forceinline__ void cp_commit() {
    asm volatile("cp.async.commit_group;\n" ::: "memory");
}
template <int N>
__device__ __forceinline__ void cp_wait() {
    asm volatile("cp.async.wait_group %0;\n" :: "n"(N) : "memory");
}

// ---------------------------------------------------------------------------
// Kernel 1: per (b, m) hyperbolic precompute.
// 3 interleaved warp reductions; |u|^2 computed analytically (no 4th).
// ---------------------------------------------------------------------------
__global__ __launch_bounds__(128) void k_hyp(
    const float* __restrict__ curr_hyp,   // [B, DH]
    const float* __restrict__ demo_hyp)   // [B, M, DH]
{
    int warp = threadIdx.x >> 5, lane = threadIdx.x & 31;
    int idx  = blockIdx.x * 4 + warp;     // [0, B*M)
    int b    = idx >> 9;                  // Mq = 512

    const float2 xv = ((const float2*)(curr_hyp + (size_t)b * DH))[lane];
    const float2 yv = ((const float2*)(demo_hyp + (size_t)idx * DH))[lane];

    float pxn = fmaf(xv.x, xv.x, xv.y * xv.y);
    float pyn = fmaf(yv.x, yv.x, yv.y * yv.y);
    float pxy = fmaf(xv.x, yv.x, xv.y * yv.y);
#pragma unroll
    for (int o = 16; o; o >>= 1) {        // 3 independent chains, interleaved
        pxn += __shfl_xor_sync(0xffffffffu, pxn, o);
        pyn += __shfl_xor_sync(0xffffffffu, pyn, o);
        pxy += __shfl_xor_sync(0xffffffffu, pxy, o);
    }

    float xnorm = fmaxf(sqrtf(pxn), 1e-15f);
    float sx    = xnorm > MAXN ? MAXN / xnorm : 1.0f;
    float ynorm = fmaxf(sqrtf(pyn), 1e-15f);
    float sy    = ynorm > MAXN ? MAXN / ynorm : 1.0f;

    float x2 = pxn * sx * sx, y2 = pyn * sy * sy, xy = pxy * sx * sy;

    float cA  = 1.0f - 2.0f * xy + y2;    // coeff of a = -x
    float cY  = 1.0f - x2;                // coeff of y
    float den = 1.0f - 2.0f * xy + x2 * y2;
    float id  = 1.0f / fmaxf(den, 1e-15f);

    // |u|^2 = id^2 * (cA^2 x2 - 2 cA cY xy + cY^2 y2)
    float un2   = (cA * cA * x2 - 2.0f * cA * cY * xy + cY * cY * y2) * id * id;
    float unorm = fmaxf(sqrtf(un2), 1e-15f);
    float arg   = fminf(unorm, ARGC);
    float at    = 0.5f * __logf((1.0f + arg) / (1.0f - arg));   // atanh

    // scale = (2/lam) * at / unorm,  2/lam = clip(1-x2, 1e-15)
    float scale = fmaxf(cY, 1e-15f) * at / unorm;

    float u0 = (cA * (-(xv.x * sx)) + cY * (yv.x * sy)) * id;
    float u1 = (cA * (-(xv.y * sx)) + cY * (yv.y * sy)) * id;

    ((float2*)(g_logv + (size_t)idx * DH))[lane] = make_float2(scale * u0, scale * u1);
    if (lane == 0) { float d = 2.0f * at; g_dH2[idx] = d * d; }
}

// ---------------------------------------------------------------------------
// Kernel 2: partial online-softmax attention with a depth-8 cp.async pipeline.
// One block per (b, a, s); warp w handles m = s*256 + w + 4*i, i in [0,64).
// Each lane reads only smem bytes it copied itself -> no intra-warp barrier.
// ---------------------------------------------------------------------------
__global__ __launch_bounds__(128) void k_attn_part(
    const float* __restrict__ curr_rho,   // [B, A, DE]
    const float* __restrict__ demo_rho)   // [B, M, A, DE]
{
    int bas = blockIdx.x;                 // ((b*64 + a)*SPLIT + s)
    int s   = bas & (SPLIT - 1);
    int ba  = bas >> 1;
    int b   = ba >> 6, a = ba & 63;
    int tid = threadIdx.x, warp = tid >> 5, lane = tid & 31;

    __shared__ float4 sm_rho[DEPTH][4][32];   // 16 KB
    __shared__ float2 sm_lv [DEPTH][4][32];   //  8 KB
    __shared__ float  s_dH2[MBLK];            //  1 KB

    // stage the dH2 slice for this block
    s_dH2[tid]       = g_dH2[(size_t)b * Mq + s * MBLK + tid];
    s_dH2[tid + 128] = g_dH2[(size_t)b * Mq + s * MBLK + tid + 128];
    __syncthreads();

    const float4 cr = ((const float4*)(curr_rho + ((size_t)b * Aq + a) * DE))[lane];

    const float* rho_b = demo_rho + ((size_t)b * Mq * Aq + a) * DE + 4 * lane;
    const float* lv_b  = g_logv + (size_t)b * Mq * DH + 2 * lane;
    int m0 = s * MBLK + warp;             // this warp's first m; stride 4

    // prologue: fill DEPTH-1 stages
#pragma unroll
    for (int j = 0; j < DEPTH - 1; ++j) {
        int m = m0 + 4 * j;
        cp_async16(smem_u32(&sm_rho[j][warp][lane]), rho_b + (size_t)m * Aq * DE);
        cp_async8 (smem_u32(&sm_lv [j][warp][lane]), lv_b  + (size_t)m * DH);
        cp_commit();
    }

    float  mx = -INFINITY, sm = 0.0f;
    float4 ea = make_float4(0.f, 0.f, 0.f, 0.f);
    float2 va = make_float2(0.f, 0.f);

#pragma unroll 8
    for (int i = 0; i < MPW; ++i) {
        int jn = i + DEPTH - 1;
        if (jn < MPW) {
            int m = m0 + 4 * jn;
            cp_async16(smem_u32(&sm_rho[jn & (DEPTH - 1)][warp][lane]),
                       rho_b + (size_t)m * Aq * DE);
            cp_async8 (smem_u32(&sm_lv [jn & (DEPTH - 1)][warp][lane]),
                       lv_b + (size_t)m * DH);
        }
        cp_commit();
        cp_wait<DEPTH - 1>();             // stage i complete (for this lane)

        float4 dm = sm_rho[i & (DEPTH - 1)][warp][lane];
        float2 lv = sm_lv [i & (DEPTH - 1)][warp][lane];

        float dx = cr.x - dm.x, dy = cr.y - dm.y, dz = cr.z - dm.z, dw = cr.w - dm.w;
        float esq = wredsum(fmaf(dx, dx, fmaf(dy, dy, fmaf(dz, dz, dw * dw))));
        float score = -(s_dH2[warp + 4 * i] + esq);     // LH = LE = TAU = 1

        if (score > mx) {                 // warp-uniform, rare after warmup
            float corr = __expf(mx - score);            // exp(-inf)=0 first iter
            mx = score;
            sm *= corr;
            ea.x *= corr; ea.y *= corr; ea.z *= corr; ea.w *= corr;
            va.x *= corr; va.y *= corr;
        }
        float w = __expf(score - mx);
        sm += w;
        ea.x = fmaf(w, dm.x, ea.x);
        ea.y = fmaf(w, dm.y, ea.y);
        ea.z = fmaf(w, dm.z, ea.z);
        ea.w = fmaf(w, dm.w, ea.w);
        va.x = fmaf(w, lv.x, va.x);
        va.y = fmaf(w, lv.y, va.y);
    }
    cp_wait<0>();                         // drain before exit

    // ---- merge 4 warps, write block partial (unnormalized, at block max) ----
    __shared__ float s_mx[4], s_sm[4], s_e[4][DE], s_v[4][DH];
    s_e[warp][4 * lane + 0] = ea.x;  s_e[warp][4 * lane + 1] = ea.y;
    s_e[warp][4 * lane + 2] = ea.z;  s_e[warp][4 * lane + 3] = ea.w;
    s_v[warp][2 * lane + 0] = va.x;  s_v[warp][2 * lane + 1] = va.y;
    if (lane == 0) { s_mx[warp] = mx; s_sm[warp] = sm; }
    __syncthreads();

    float gmax = fmaxf(fmaxf(s_mx[0], s_mx[1]), fmaxf(s_mx[2], s_mx[3]));
    float c0 = __expf(s_mx[0] - gmax), c1 = __expf(s_mx[1] - gmax);
    float c2 = __expf(s_mx[2] - gmax), c3 = __expf(s_mx[3] - gmax);

    g_pe[(size_t)bas * DE + tid] = s_e[0][tid] * c0 + s_e[1][tid] * c1 +
                                   s_e[2][tid] * c2 + s_e[3][tid] * c3;
    if (tid < DH)
        g_pv[(size_t)bas * DH + tid] = s_v[0][tid] * c0 + s_v[1][tid] * c1 +
                                       s_v[2][tid] * c2 + s_v[3][tid] * c3;
    if (tid == 0) {
        g_pmx[bas] = gmax;
        g_psm[bas] = s_sm[0] * c0 + s_sm[1] * c1 + s_sm[2] * c2 + s_sm[3] * c3;
    }
}

// ---------------------------------------------------------------------------
// Kernel 3: merge SPLIT partials per (b,a); exp-map, projections, LayerNorm.
// ---------------------------------------------------------------------------
__global__ __launch_bounds__(128) void k_final(
    const float* __restrict__ curr_hyp,   // [B, DH]
    const float* __restrict__ We,         // [ZE, DE]
    const float* __restrict__ Wh,         // [ZH, DH]
    const float* __restrict__ gamma,      // [ZDIM]
    const float* __restrict__ beta,       // [ZDIM]
    float* __restrict__ out)              // [B, A, ZDIM]
{
    int ba = blockIdx.x;                  // b*64 + a
    int b  = ba >> 6;
    int tid = threadIdx.x, warp = tid >> 5, lane = tid & 31;

    __shared__ float s_eout[DE], s_vv[DH], s_h[DH], s_wred[4];

    float mx0 = g_pmx[ba * SPLIT + 0], mx1 = g_pmx[ba * SPLIT + 1];
    float G = fmaxf(mx0, mx1);
    float c0 = __expf(mx0 - G), c1 = __expf(mx1 - G);
    float inv = 1.0f / (g_psm[ba * SPLIT + 0] * c0 + g_psm[ba * SPLIT + 1] * c1);

    s_eout[tid] = (g_pe[((size_t)ba * SPLIT + 0) * DE + tid] * c0 +
                   g_pe[((size_t)ba * SPLIT + 1) * DE + tid] * c1) * inv;
    if (tid < DH)
        s_vv[tid] = (g_pv[((size_t)ba * SPLIT + 0) * DH + tid] * c0 +
                     g_pv[((size_t)ba * SPLIT + 1) * DH + tid] * c1) * inv;
    __syncthreads();

    // ---- exp-map (warp 0; lane owns dims lane and lane+32) ----
    if (warp == 0) {
        float x0 = curr_hyp[b * DH + lane], x1 = curr_hyp[b * DH + lane + 32];
        float xn2   = wredsum(x0 * x0 + x1 * x1);
        float xnorm = fmaxf(sqrtf(xn2), 1e-15f);
        float sx    = xnorm > MAXN ? MAXN / xnorm : 1.0f;
        x0 *= sx; x1 *= sx;
        float x2  = xn2 * sx * sx;
        float lam = 2.0f / fmaxf(1.0f - x2, 1e-15f);

        float v0 = s_vv[lane], v1 = s_vv[lane + 32];
        float vn2    = wredsum(v0 * v0 + v1 * v1);
        float vnorm  = fmaxf(sqrtf(vn2), 1e-15f);
        float factor = tanhf(lam * vnorm * 0.5f);
        float f      = factor / vnorm;
        float y0 = v0 * f, y1 = v1 * f;

        float yn2   = wredsum(y0 * y0 + y1 * y1);
        float ynorm = fmaxf(sqrtf(yn2), 1e-15f);
        float sy    = ynorm > MAXN ? MAXN / ynorm : 1.0f;
        y0 *= sy; y1 *= sy;
        float y2s = yn2 * sy * sy;

        float xy  = wredsum(x0 * y0 + x1 * y1);
        float cA  = 1.0f + 2.0f * xy + y2s;
        float cY  = 1.0f - x2;
        float den = 1.0f + 2.0f * xy + x2 * y2s;
        float id  = 1.0f / fmaxf(den, 1e-15f);
        float o0  = (cA * x0 + cY * y0) * id;
        float o1  = (cA * x1 + cY * y1) * id;

        float on2   = wredsum(o0 * o0 + o1 * o1);
        float onorm = fmaxf(sqrtf(on2), 1e-15f);
        float so    = onorm > MAXN ? MAXN / onorm : 1.0f;
        s_h[lane] = o0 * so; s_h[lane + 32] = o1 * so;
    }
    __syncthreads();

    // ---- projections z = [e_out @ We^T, h_out @ Wh^T] ----
    float z;
    if (tid < ZE) {
        const float4* wr = (const float4*)(We + (size_t)tid * DE);
        float acc = 0.f;
#pragma unroll
        for (int k = 0; k < DE / 4; k++) {
            float4 wv = wr[k];
            acc += wv.x * s_eout[4 * k]     + wv.y * s_eout[4 * k + 1]
                 + wv.z * s_eout[4 * k + 2] + wv.w * s_eout[4 * k + 3];
        }
        z = acc;
    } else {
        const float4* wr = (const float4*)(Wh + (size_t)(tid - ZE) * DH);
        float acc = 0.f;
#pragma unroll
        for (int k = 0; k < DH / 4; k++) {
            float4 wv = wr[k];
            acc += wv.x * s_h[4 * k]     + wv.y * s_h[4 * k + 1]
                 + wv.z * s_h[4 * k + 2] + wv.w * s_h[4 * k + 3];
        }
        z = acc;
    }

    // ---- LayerNorm over ZDIM = 128 threads ----
    float p = wredsum(z);
    if (lane == 0) s_wred[warp] = p;
    __syncthreads();
    float mean = (s_wred[0] + s_wred[1] + s_wred[2] + s_wred[3]) * (1.0f / ZDIM);
    float dz = z - mean;
    float q = wredsum(dz * dz);
    __syncthreads();
    if (lane == 0) s_wred[warp] = q;
    __syncthreads();
    float var = (s_wred[0] + s_wred[1] + s_wred[2] + s_wred[3]) * (1.0f / ZDIM);

    out[(size_t)ba * ZDIM + tid] = dz / sqrtf(var + 1e-5f) * gamma[tid] + beta[tid];
}

// ---------------------------------------------------------------------------
extern "C" void kernel_launch(void* const* d_in, const int* in_sizes, int n_in,
                              void* d_out, int out_size)
{
    const float* curr_rho = (const float*)d_in[0];   // [B,A,de]
    const float* curr_hyp = (const float*)d_in[1];   // [B,dh]
    const float* demo_rho = (const float*)d_in[2];   // [B,N,L,A,de]
    const float* demo_hyp = (const float*)d_in[3];   // [B,N,L,dh]
    const float* We       = (const float*)d_in[4];   // [z_e,de]
    const float* Wh       = (const float*)d_in[5];   // [z_h,dh]
    const float* gamma    = (const float*)d_in[6];   // [z]
    const float* beta     = (const float*)d_in[7];   // [z]
    float* out = (float*)d_out;

    k_hyp<<<(Bq * Mq) / 4, 128>>>(curr_hyp, demo_hyp);
    k_attn_part<<<Bq * Aq * SPLIT, 128>>>(curr_rho, demo_rho);
    k_final<<<Bq * Aq, 128>>>(curr_hyp, We, Wh, gamma, beta, out);
}

// round 8
// speedup vs baseline: 1.8237x; 1.0435x over previous
#include <cuda_runtime.h>
#include <math.h>
#include <stdint.h>

// Problem constants (fixed by the dataset shapes)
#define Bq    8
#define Aq    64
#define DE    128
#define DH    64
#define Mq    512            // N*L = 8*64
#define ZDIM  128
#define ZE    64
#define ZH    64
#define SPLIT 4              // m-splits per (b,a)
#define MBLK  (Mq / SPLIT)   // 128 m per block
#define MPW   (MBLK / 4)     // 32 m per warp
#define CHUNK 4              // m processed per loop step
#define NCHUNK (MPW / CHUNK) // 8
#define MAXN  0.99999f       // (1 - 1e-5)/sqrt(c), c = 1
#define ARGC  0.9999999f     // 1 - 1e-7

// Scratch (device globals: no allocation in kernel_launch)
__device__ float g_dH2[Bq * Mq];                       // 16 KB
__device__ float g_logv[Bq * Mq * DH];                 // 1 MB
__device__ float g_pmx[Bq * Aq * SPLIT];               // partial max
__device__ float g_psm[Bq * Aq * SPLIT];               // partial sum-exp
__device__ float g_pe [Bq * Aq * SPLIT * DE];          // partial e-acc
__device__ float g_pv [Bq * Aq * SPLIT * DH];          // partial v-acc

__device__ __forceinline__ float wredsum(float v) {
#pragma unroll
    for (int o = 16; o; o >>= 1) v += __shfl_xor_sync(0xffffffffu, v, o);
    return v;
}

__device__ __forceinline__ uint32_t smem_u32(const void* p) {
    return (uint32_t)__cvta_generic_to_shared(p);
}
__device__ __forceinline__ void cp_async16(uint32_t dst, const void* src) {
    asm volatile("cp.async.cg.shared.global [%0], [%1], 16;\n" :: "r"(dst), "l"(src));
}
__device__ __forceinline__ void cp_async8(uint32_t dst, const void* src) {
    asm volatile("cp.async.ca.shared.global [%0], [%1], 8;\n" :: "r"(dst), "l"(src));
}
__device__ __forceinline__ void cp_commit() {
    asm volatile("cp.async.commit_group;\n" ::: "memory");
}
template <int N>
__device__ __forceinline__ void cp_wait() {
    asm volatile("cp.async.wait_group %0;\n" :: "n"(N) : "memory");
}

// ---------------------------------------------------------------------------
// Kernel 1: per (b, m) hyperbolic precompute (3 interleaved warp reductions,
// analytic |u|^2, fast divides — error budget is 1e-3, we sit at ~5e-6).
// ---------------------------------------------------------------------------
__global__ __launch_bounds__(128) void k_hyp(
    const float* __restrict__ curr_hyp,   // [B, DH]
    const float* __restrict__ demo_hyp)   // [B, M, DH]
{
    int warp = threadIdx.x >> 5, lane = threadIdx.x & 31;
    int idx  = blockIdx.x * 4 + warp;     // [0, B*M)
    int b    = idx >> 9;                  // Mq = 512

    const float2 xv = ((const float2*)(curr_hyp + (size_t)b * DH))[lane];
    const float2 yv = ((const float2*)(demo_hyp + (size_t)idx * DH))[lane];

    float pxn = fmaf(xv.x, xv.x, xv.y * xv.y);
    float pyn = fmaf(yv.x, yv.x, yv.y * yv.y);
    float pxy = fmaf(xv.x, yv.x, xv.y * yv.y);
#pragma unroll
    for (int o = 16; o; o >>= 1) {        // 3 independent chains, interleaved
        pxn += __shfl_xor_sync(0xffffffffu, pxn, o);
        pyn += __shfl_xor_sync(0xffffffffu, pyn, o);
        pxy += __shfl_xor_sync(0xffffffffu, pxy, o);
    }

    float xnorm = fmaxf(sqrtf(pxn), 1e-15f);
    float sx    = xnorm > MAXN ? __fdividef(MAXN, xnorm) : 1.0f;
    float ynorm = fmaxf(sqrtf(pyn), 1e-15f);
    float sy    = ynorm > MAXN ? __fdividef(MAXN, ynorm) : 1.0f;

    float x2 = pxn * sx * sx, y2 = pyn * sy * sy, xy = pxy * sx * sy;

    float cA  = 1.0f - 2.0f * xy + y2;    // coeff of a = -x
    float cY  = 1.0f - x2;                // coeff of y
    float den = 1.0f - 2.0f * xy + x2 * y2;
    float id  = __fdividef(1.0f, fmaxf(den, 1e-15f));

    // |u|^2 = id^2 * (cA^2 x2 - 2 cA cY xy + cY^2 y2)
    float un2   = (cA * cA * x2 - 2.0f * cA * cY * xy + cY * cY * y2) * id * id;
    float unorm = fmaxf(sqrtf(un2), 1e-15f);
    float arg   = fminf(unorm, ARGC);
    float at    = 0.5f * __logf(__fdividef(1.0f + arg, 1.0f - arg));   // atanh

    // scale = (2/lam) * at / unorm,  2/lam = clip(1-x2, 1e-15)
    float scale = fmaxf(cY, 1e-15f) * __fdividef(at, unorm);

    float u0 = (cA * (-(xv.x * sx)) + cY * (yv.x * sy)) * id;
    float u1 = (cA * (-(xv.y * sx)) + cY * (yv.y * sy)) * id;

    ((float2*)(g_logv + (size_t)idx * DH))[lane] = make_float2(scale * u0, scale * u1);
    if (lane == 0) { float d = 2.0f * at; g_dH2[idx] = d * d; }
}

// ---------------------------------------------------------------------------
// Kernel 2: partial online-softmax attention, CHUNK=4 m per step,
// 2-chunk (8 m-slot) cp.async ring. One block per (b, a, s);
// warp w handles m = s*128 + w + 4*i. Each lane reads only smem bytes it
// copied itself -> no intra-warp barrier needed.
// ---------------------------------------------------------------------------
__global__ __launch_bounds__(128) void k_attn_part(
    const float* __restrict__ curr_rho,   // [B, A, DE]
    const float* __restrict__ demo_rho)   // [B, M, A, DE]
{
    int bas = blockIdx.x;                 // ((b*64 + a)*SPLIT + s)
    int s   = bas & (SPLIT - 1);
    int ba  = bas >> 2;
    int b   = ba >> 6, a = ba & 63;
    int tid = threadIdx.x, warp = tid >> 5, lane = tid & 31;

    __shared__ float4 sm_rho[8][4][32];   // 16 KB (8 m-slots)
    __shared__ float2 sm_lv [8][4][32];   //  8 KB
    __shared__ float  s_dH2[MBLK];        // 512 B

    s_dH2[tid] = g_dH2[(size_t)b * Mq + s * MBLK + tid];
    __syncthreads();

    const float4 cr = ((const float4*)(curr_rho + ((size_t)b * Aq + a) * DE))[lane];

    const float* rho_b = demo_rho + ((size_t)b * Mq * Aq + a) * DE + 4 * lane;
    const float* lv_b  = g_logv + (size_t)b * Mq * DH + 2 * lane;
    int m0 = s * MBLK + warp;             // this warp's first m; stride 4

    // prologue: fill 2 chunks (one commit group per chunk)
#pragma unroll
    for (int c = 0; c < 2; ++c) {
#pragma unroll
        for (int j = 0; j < CHUNK; ++j) {
            int m = m0 + 16 * c + 4 * j;
            cp_async16(smem_u32(&sm_rho[4 * c + j][warp][lane]),
                       rho_b + (size_t)m * Aq * DE);
            cp_async8 (smem_u32(&sm_lv [4 * c + j][warp][lane]),
                       lv_b + (size_t)m * DH);
        }
        cp_commit();
    }

    float  mx = -INFINITY, sm = 0.0f;
    float4 ea = make_float4(0.f, 0.f, 0.f, 0.f);
    float2 va = make_float2(0.f, 0.f);

#pragma unroll
    for (int ci = 0; ci < NCHUNK; ++ci) {
        cp_wait<1>();                     // chunk ci resident (for this lane)
        int slot = (ci & 1) * CHUNK;

        float4 dm[CHUNK]; float2 lv[CHUNK];
#pragma unroll
        for (int j = 0; j < CHUNK; ++j) {
            dm[j] = sm_rho[slot + j][warp][lane];
            lv[j] = sm_lv [slot + j][warp][lane];
        }

        // refill the freed slot with chunk ci+2
        if (ci + 2 < NCHUNK) {
#pragma unroll
            for (int j = 0; j < CHUNK; ++j) {
                int m = m0 + 16 * (ci + 2) + 4 * j;
                cp_async16(smem_u32(&sm_rho[slot + j][warp][lane]),
                           rho_b + (size_t)m * Aq * DE);
                cp_async8 (smem_u32(&sm_lv [slot + j][warp][lane]),
                           lv_b + (size_t)m * DH);
            }
        }
        cp_commit();                      // (possibly empty) keeps group count

        // 4 partial squared distances, interleaved butterfly
        float p[CHUNK];
#pragma unroll
        for (int j = 0; j < CHUNK; ++j) {
            float dx = cr.x - dm[j].x, dy = cr.y - dm[j].y;
            float dz = cr.z - dm[j].z, dw = cr.w - dm[j].w;
            p[j] = fmaf(dx, dx, fmaf(dy, dy, fmaf(dz, dz, dw * dw)));
        }
#pragma unroll
        for (int o = 16; o; o >>= 1) {
#pragma unroll
            for (int j = 0; j < CHUNK; ++j)
                p[j] += __shfl_xor_sync(0xffffffffu, p[j], o);
        }

        float sc[CHUNK];
#pragma unroll
        for (int j = 0; j < CHUNK; ++j)
            sc[j] = -(s_dH2[warp + 16 * ci + 4 * j] + p[j]);   // LH=LE=TAU=1

        float cm = fmaxf(fmaxf(sc[0], sc[1]), fmaxf(sc[2], sc[3]));
        if (cm > mx) {                    // warp-uniform; once per 4 m
            float corr = __expf(mx - cm); // exp(-inf)=0 on first chunk
            mx = cm;
            sm *= corr;
            ea.x *= corr; ea.y *= corr; ea.z *= corr; ea.w *= corr;
            va.x *= corr; va.y *= corr;
        }
#pragma unroll
        for (int j = 0; j < CHUNK; ++j) {
            float w = __expf(sc[j] - mx);
            sm += w;
            ea.x = fmaf(w, dm[j].x, ea.x);
            ea.y = fmaf(w, dm[j].y, ea.y);
            ea.z = fmaf(w, dm[j].z, ea.z);
            ea.w = fmaf(w, dm[j].w, ea.w);
            va.x = fmaf(w, lv[j].x, va.x);
            va.y = fmaf(w, lv[j].y, va.y);
        }
    }
    cp_wait<0>();                         // drain before smem reuse

    // ---- merge 4 warps, write block partial (unnormalized, at block max) ----
    __shared__ float s_mx[4], s_sm[4], s_e[4][DE], s_v[4][DH];
    s_e[warp][4 * lane + 0] = ea.x;  s_e[warp][4 * lane + 1] = ea.y;
    s_e[warp][4 * lane + 2] = ea.z;  s_e[warp][4 * lane + 3] = ea.w;
    s_v[warp][2 * lane + 0] = va.x;  s_v[warp][2 * lane + 1] = va.y;
    if (lane == 0) { s_mx[warp] = mx; s_sm[warp] = sm; }
    __syncthreads();

    float gmax = fmaxf(fmaxf(s_mx[0], s_mx[1]), fmaxf(s_mx[2], s_mx[3]));
    float c0 = __expf(s_mx[0] - gmax), c1 = __expf(s_mx[1] - gmax);
    float c2 = __expf(s_mx[2] - gmax), c3 = __expf(s_mx[3] - gmax);

    g_pe[(size_t)bas * DE + tid] = s_e[0][tid] * c0 + s_e[1][tid] * c1 +
                                   s_e[2][tid] * c2 + s_e[3][tid] * c3;
    if (tid < DH)
        g_pv[(size_t)bas * DH + tid] = s_v[0][tid] * c0 + s_v[1][tid] * c1 +
                                       s_v[2][tid] * c2 + s_v[3][tid] * c3;
    if (tid == 0) {
        g_pmx[bas] = gmax;
        g_psm[bas] = s_sm[0] * c0 + s_sm[1] * c1 + s_sm[2] * c2 + s_sm[3] * c3;
    }
}

// ---------------------------------------------------------------------------
// Kernel 3: merge SPLIT partials per (b,a); exp-map, projections, LayerNorm.
// ---------------------------------------------------------------------------
__global__ __launch_bounds__(128) void k_final(
    const float* __restrict__ curr_hyp,   // [B, DH]
    const float* __restrict__ We,         // [ZE, DE]
    const float* __restrict__ Wh,         // [ZH, DH]
    const float* __restrict__ gamma,      // [ZDIM]
    const float* __restrict__ beta,       // [ZDIM]
    float* __restrict__ out)              // [B, A, ZDIM]
{
    int ba = blockIdx.x;                  // b*64 + a
    int b  = ba >> 6;
    int tid = threadIdx.x, warp = tid >> 5, lane = tid & 31;

    __shared__ float s_eout[DE], s_vv[DH], s_h[DH], s_wred[4];

    float mx0 = g_pmx[ba * SPLIT + 0], mx1 = g_pmx[ba * SPLIT + 1];
    float mx2 = g_pmx[ba * SPLIT + 2], mx3 = g_pmx[ba * SPLIT + 3];
    float G = fmaxf(fmaxf(mx0, mx1), fmaxf(mx2, mx3));
    float c0 = __expf(mx0 - G), c1 = __expf(mx1 - G);
    float c2 = __expf(mx2 - G), c3 = __expf(mx3 - G);
    float inv = __fdividef(1.0f,
        g_psm[ba * SPLIT + 0] * c0 + g_psm[ba * SPLIT + 1] * c1 +
        g_psm[ba * SPLIT + 2] * c2 + g_psm[ba * SPLIT + 3] * c3);

    s_eout[tid] = (g_pe[((size_t)ba * SPLIT + 0) * DE + tid] * c0 +
                   g_pe[((size_t)ba * SPLIT + 1) * DE + tid] * c1 +
                   g_pe[((size_t)ba * SPLIT + 2) * DE + tid] * c2 +
                   g_pe[((size_t)ba * SPLIT + 3) * DE + tid] * c3) * inv;
    if (tid < DH)
        s_vv[tid] = (g_pv[((size_t)ba * SPLIT + 0) * DH + tid] * c0 +
                     g_pv[((size_t)ba * SPLIT + 1) * DH + tid] * c1 +
                     g_pv[((size_t)ba * SPLIT + 2) * DH + tid] * c2 +
                     g_pv[((size_t)ba * SPLIT + 3) * DH + tid] * c3) * inv;
    __syncthreads();

    // ---- exp-map (warp 0; lane owns dims lane and lane+32) ----
    if (warp == 0) {
        float x0 = curr_hyp[b * DH + lane], x1 = curr_hyp[b * DH + lane + 32];
        float xn2   = wredsum(x0 * x0 + x1 * x1);
        float xnorm = fmaxf(sqrtf(xn2), 1e-15f);
        float sx    = xnorm > MAXN ? __fdividef(MAXN, xnorm) : 1.0f;
        x0 *= sx; x1 *= sx;
        float x2  = xn2 * sx * sx;
        float lam = 2.0f * __fdividef(1.0f, fmaxf(1.0f - x2, 1e-15f));

        float v0 = s_vv[lane], v1 = s_vv[lane + 32];
        float vn2    = wredsum(v0 * v0 + v1 * v1);
        float vnorm  = fmaxf(sqrtf(vn2), 1e-15f);
        float factor = tanhf(lam * vnorm * 0.5f);
        float f      = __fdividef(factor, vnorm);
        float y0 = v0 * f, y1 = v1 * f;

        float yn2   = wredsum(y0 * y0 + y1 * y1);
        float ynorm = fmaxf(sqrtf(yn2), 1e-15f);
        float sy    = ynorm > MAXN ? __fdividef(MAXN, ynorm) : 1.0f;
        y0 *= sy; y1 *= sy;
        float y2s = yn2 * sy * sy;

        float xy  = wredsum(x0 * y0 + x1 * y1);
        float cA  = 1.0f + 2.0f * xy + y2s;
        float cY  = 1.0f - x2;
        float den = 1.0f + 2.0f * xy + x2 * y2s;
        float id  = __fdividef(1.0f, fmaxf(den, 1e-15f));
        float o0  = (cA * x0 + cY * y0) * id;
        float o1  = (cA * x1 + cY * y1) * id;

        float on2   = wredsum(o0 * o0 + o1 * o1);
        float onorm = fmaxf(sqrtf(on2), 1e-15f);
        float so    = onorm > MAXN ? __fdividef(MAXN, onorm) : 1.0f;
        s_h[lane] = o0 * so; s_h[lane + 32] = o1 * so;
    }
    __syncthreads();

    // ---- projections z = [e_out @ We^T, h_out @ Wh^T] ----
    float z;
    if (tid < ZE) {
        const float4* wr = (const float4*)(We + (size_t)tid * DE);
        float acc = 0.f;
#pragma unroll
        for (int k = 0; k < DE / 4; k++) {
            float4 wv = wr[k];
            acc += wv.x * s_eout[4 * k]     + wv.y * s_eout[4 * k + 1]
                 + wv.z * s_eout[4 * k + 2] + wv.w * s_eout[4 * k + 3];
        }
        z = acc;
    } else {
        const float4* wr = (const float4*)(Wh + (size_t)(tid - ZE) * DH);
        float acc = 0.f;
#pragma unroll
        for (int k = 0; k < DH / 4; k++) {
            float4 wv = wr[k];
            acc += wv.x * s_h[4 * k]     + wv.y * s_h[4 * k + 1]
                 + wv.z * s_h[4 * k + 2] + wv.w * s_h[4 * k + 3];
        }
        z = acc;
    }

    // ---- LayerNorm over ZDIM = 128 threads ----
    float p = wredsum(z);
    if (lane == 0) s_wred[warp] = p;
    __syncthreads();
    float mean = (s_wred[0] + s_wred[1] + s_wred[2] + s_wred[3]) * (1.0f / ZDIM);
    float dz = z - mean;
    float q = wredsum(dz * dz);
    __syncthreads();
    if (lane == 0) s_wred[warp] = q;
    __syncthreads();
    float var = (s_wred[0] + s_wred[1] + s_wred[2] + s_wred[3]) * (1.0f / ZDIM);

    out[(size_t)ba * ZDIM + tid] = dz * __frsqrt_rn(var + 1e-5f) * gamma[tid] + beta[tid];
}

// ---------------------------------------------------------------------------
extern "C" void kernel_launch(void* const* d_in, const int* in_sizes, int n_in,
                              void* d_out, int out_size)
{
    const float* curr_rho = (const float*)d_in[0];   // [B,A,de]
    const float* curr_hyp = (const float*)d_in[1];   // [B,dh]
    const float* demo_rho = (const float*)d_in[2];   // [B,N,L,A,de]
    const float* demo_hyp = (const float*)d_in[3];   // [B,N,L,dh]
    const float* We       = (const float*)d_in[4];   // [z_e,de]
    const float* Wh       = (const float*)d_in[5];   // [z_h,dh]
    const float* gamma    = (const float*)d_in[6];   // [z]
    const float* beta     = (const float*)d_in[7];   // [z]
    float* out = (float*)d_out;

    k_hyp<<<(Bq * Mq) / 4, 128>>>(curr_hyp, demo_hyp);
    k_attn_part<<<Bq * Aq * SPLIT, 128>>>(curr_rho, demo_rho);
    k_final<<<Bq * Aq, 128>>>(curr_hyp, We, Wh, gamma, beta, out);
}